// round 2
// baseline (speedup 1.0000x reference)
#include <cuda_runtime.h>
#include <stdint.h>

#define B_ 4
#define V_ 778
#define F_ 1538
#define S_ 320
#define TILE 32          // 32x32 pixel tile per block
#define FPW 193          // ceil(F_/8) faces per warp cull segment

// Per (batch, face): 3 edges x (A, B, C, pad). d = A*px + B*py + C, scaled by
// sgn * inv_len * log2(e) / sigma, so exp2(-d) = exp(-dist/sigma).
__device__ float g_coeffs[B_ * F_ * 12];

__global__ void precompute_kernel(const float* __restrict__ verts,
                                  const int* __restrict__ faces) {
    int idx = blockIdx.x * blockDim.x + threadIdx.x;
    if (idx >= B_ * F_) return;
    int b = idx / F_;
    int f = idx - b * F_;
    int i0 = faces[f * 3 + 0], i1 = faces[f * 3 + 1], i2 = faces[f * 3 + 2];
    const float* vb = verts + b * V_ * 3;
    float x0 = vb[i0 * 3 + 0], y0 = -vb[i0 * 3 + 1];
    float x1 = vb[i1 * 3 + 0], y1 = -vb[i1 * 3 + 1];
    float x2 = vb[i2 * 3 + 0], y2 = -vb[i2 * 3 + 1];
    float area2 = (x1 - x0) * (y2 - y0) - (y1 - y0) * (x2 - x0);
    float sgn = (area2 > 0.f) ? 1.f : ((area2 < 0.f) ? -1.f : 0.f);
    const float INVS = 1.4426950408889634f / 0.01f;  // log2(e)/SIGMA

    float ax[3] = {x0, x1, x2}, ay[3] = {y0, y1, y2};
    float bx[3] = {x1, x2, x0}, by[3] = {y1, y2, y0};
    float* o = g_coeffs + idx * 12;
#pragma unroll
    for (int e = 0; e < 3; e++) {
        float ex = bx[e] - ax[e];
        float ey = by[e] - ay[e];
        float inv_len = 1.0f / (sqrtf(ex * ex + ey * ey) + 1e-8f);
        float k = sgn * inv_len * INVS;
        o[e * 4 + 0] = -k * ey;
        o[e * 4 + 1] = k * ex;
        o[e * 4 + 2] = k * (ey * ax[e] - ex * ay[e]);
        o[e * 4 + 3] = 0.f;
    }
}

__device__ __forceinline__ float ex2f(float x) {
    float r; asm("ex2.approx.ftz.f32 %0, %1;" : "=f"(r) : "f"(x)); return r;
}
__device__ __forceinline__ float rcpf(float x) {
    float r; asm("rcp.approx.ftz.f32 %0, %1;" : "=f"(r) : "f"(x)); return r;
}

__global__ __launch_bounds__(256) void silhouette_kernel(float* __restrict__ out) {
    __shared__ uint16_t s_idx[8 * FPW];
    __shared__ int s_cnt[8];
    __shared__ int s_deep;

    const int tid = threadIdx.x;
    const int w = tid >> 5;          // warp: owns rows 4w..4w+3
    const int lane = tid & 31;       // lane: x within tile
    const int b = blockIdx.z;
    const int x0 = blockIdx.x * TILE;
    const int y0 = blockIdx.y * TILE;

    if (tid == 0) s_deep = 0;
    __syncthreads();

    // thresholds in (dist/sigma)*log2(e) units
    const float DEAD = -15.8696454f;   // -11 * log2e : skip err <= 1.7e-5
    const float DEEP = 21.6404256f;    //  15 * log2e : Q <= 9.2e-7 < RMIN bound
    const float STEP = 2.0f / S_;

    // ---------- Phase A: per-warp tile culling ----------
    {
        const float cx = (x0 + 16.5f) * STEP - 1.0f;
        const float cy = (y0 + 16.5f) * STEP - 1.0f;
        const float hx = 15.5f * STEP + 1e-4f;
        const float hy = hx;

        const float* cb = g_coeffs + (size_t)b * F_ * 12;
        int lo = w * FPW;
        int hi = min(lo + FPW, F_);
        int cnt = 0, ndeep = 0;
        for (int base = lo; base < hi; base += 32) {
            int f = base + lane;
            bool active = false, deep = false;
            if (f < hi) {
                const float4* cp = (const float4*)(cb + (size_t)f * 12);
                float4 e0 = cp[0], e1 = cp[1], e2 = cp[2];
                float dc0 = fmaf(e0.x, cx, fmaf(e0.y, cy, e0.z));
                float dc1 = fmaf(e1.x, cx, fmaf(e1.y, cy, e1.z));
                float dc2 = fmaf(e2.x, cx, fmaf(e2.y, cy, e2.z));
                float ex0 = fmaf(fabsf(e0.x), hx, fabsf(e0.y) * hy);
                float ex1 = fmaf(fabsf(e1.x), hx, fabsf(e1.y) * hy);
                float ex2_ = fmaf(fabsf(e2.x), hx, fabsf(e2.y) * hy);
                bool dead = (dc0 + ex0 < DEAD) || (dc1 + ex1 < DEAD) || (dc2 + ex2_ < DEAD);
                deep = (dc0 - ex0 > DEEP) && (dc1 - ex1 > DEEP) && (dc2 - ex2_ > DEEP);
                active = !dead && !deep;
            }
            unsigned balA = __ballot_sync(0xffffffffu, active);
            if (active) {
                int pos = cnt + __popc(balA & ((1u << lane) - 1u));
                s_idx[lo % (8 * FPW) == lo ? lo + pos : lo + pos] = (uint16_t)f;
            }
            cnt += __popc(balA);
            unsigned balD = __ballot_sync(0xffffffffu, deep);
            if (lane == 0) ndeep += __popc(balD);
        }
        if (lane == 0) {
            s_cnt[w] = cnt;
            atomicAdd(&s_deep, ndeep);
        }
    }
    __syncthreads();

    // ---------- Phase B: 4 pixels (contiguous rows) per thread ----------
    const int pxi = x0 + lane;
    const int ry = y0 + 4 * w;                       // first of 4 rows
    const float px = (pxi + 0.5f) * STEP - 1.0f;
    const float py0 = (ry + 0.5f) * STEP - 1.0f;
    const float py3 = (ry + 3.5f) * STEP - 1.0f;

    const float CLIPV = 1.0f - 1e-6f;
    const float RMIN = 1.0f - CLIPV;

    float W0 = 1.f, W1 = 1.f, W2 = 1.f, W3 = 1.f;
    {
        int nd = s_deep;
        if (nd >= 8) { W0 = W1 = W2 = W3 = 0.0f; }
        else { for (int i = 0; i < nd; i++) { W0 *= RMIN; } W1 = W2 = W3 = W0; }
    }

    const float* cb = g_coeffs + (size_t)b * F_ * 12;
#pragma unroll 1
    for (int s = 0; s < 8; s++) {
        int n = s_cnt[s];
        const uint16_t* ip = s_idx + s * FPW;
#pragma unroll 1
        for (int j = 0; j < n; j++) {
            int f = ip[j];
            const float4* cp = (const float4*)(cb + (size_t)f * 12);
            float4 e0 = __ldg(cp), e1 = __ldg(cp + 1), e2 = __ldg(cp + 2);
            // d at top row (k=0) and bottom row (k=3); d is linear in py
            float u0 = fmaf(e0.x, px, e0.z);
            float u1 = fmaf(e1.x, px, e1.z);
            float u2 = fmaf(e2.x, px, e2.z);
            float a0 = fmaf(e0.y, py0, u0), b0v = fmaf(e0.y, py3, u0);
            float a1 = fmaf(e1.y, py0, u1), b1v = fmaf(e1.y, py3, u1);
            float a2 = fmaf(e2.y, py0, u2), b2v = fmaf(e2.y, py3, u2);
            float hi0 = fmaxf(a0, b0v), lo0 = fminf(a0, b0v);
            float hi1 = fmaxf(a1, b1v), lo1 = fminf(a1, b1v);
            float hi2 = fmaxf(a2, b2v), lo2 = fminf(a2, b2v);

            // all 4 pixels dead for this face?
            if (hi0 < DEAD || hi1 < DEAD || hi2 < DEAD) continue;
            // all 4 pixels deep inside? exact clipped constant
            if (lo0 > DEEP && lo1 > DEEP && lo2 > DEEP) {
                W0 *= RMIN; W1 *= RMIN; W2 *= RMIN; W3 *= RMIN;
                continue;
            }

            float dl0 = e0.y * STEP, dl1 = e1.y * STEP, dl2 = e2.y * STEP;
            float d0 = a0, d1 = a1, d2 = a2;
#pragma unroll
            for (int k = 0; k < 4; k++) {
                float mn01 = fminf(d0, d1), mx01 = fmaxf(d0, d1);
                float dmin = fminf(mn01, d2);
                float dmid = fmaxf(fminf(mx01, d2), mn01);
                if (dmin > DEAD) {
                    float r;
                    if (dmid > DEEP) {
                        if (dmin > DEEP) {
                            r = RMIN;   // deep pixel: clipped constant, no MUFU
                        } else {
                            // single relevant edge: r = t/(1+t)
                            float t = ex2f(-dmin);
                            r = fmaxf(t * rcpf(1.0f + t), RMIN);
                        }
                    } else {
                        float t0 = ex2f(-d0);
                        float t1 = ex2f(-d1);
                        float t2 = ex2f(-d2);
                        float sA = t1 + t2;
                        float pA = t1 * t2;
                        float sp = sA + pA;
                        float Q = fmaf(t0, sp, t0 + sp);
                        r = Q * rcpf(1.0f + Q);
                        r = fminf(fmaxf(r, RMIN), 1.0f);
                    }
                    if (k == 0) W0 *= r;
                    else if (k == 1) W1 *= r;
                    else if (k == 2) W2 *= r;
                    else W3 *= r;
                }
                d0 += dl0; d1 += dl1; d2 += dl2;
            }
        }
    }

    float* op = out + ((size_t)b * S_ + ry) * S_ + pxi;
    op[0] = 1.0f - W0;
    op[S_] = 1.0f - W1;
    op[2 * S_] = 1.0f - W2;
    op[3 * S_] = 1.0f - W3;
}

extern "C" void kernel_launch(void* const* d_in, const int* in_sizes, int n_in,
                              void* d_out, int out_size) {
    const float* verts = (const float*)d_in[0];
    const int* faces = (const int*)d_in[1];
    float* out = (float*)d_out;

    int total = B_ * F_;
    precompute_kernel<<<(total + 255) / 256, 256>>>(verts, faces);

    dim3 grid(S_ / TILE, S_ / TILE, B_);
    silhouette_kernel<<<grid, 256>>>(out);
}

// round 3
// speedup vs baseline: 2.4905x; 2.4905x over previous
#include <cuda_runtime.h>
#include <stdint.h>

#define B_ 4
#define V_ 778
#define F_ 1538
#define S_ 320
#define TILE 16
#define CHUNK 256      // faces culled/compacted per pass (== blockDim)

// Per (batch, face): 3 edges x (A, B, C, pad). d = A*px + B*py + C, scaled by
// sgn * inv_len * log2(e) / sigma, so exp2(-d) = exp(-dist/sigma).
__device__ float g_coeffs[B_ * F_ * 12];

__global__ void precompute_kernel(const float* __restrict__ verts,
                                  const int* __restrict__ faces) {
    int idx = blockIdx.x * blockDim.x + threadIdx.x;
    if (idx >= B_ * F_) return;
    int b = idx / F_;
    int f = idx - b * F_;
    int i0 = faces[f * 3 + 0], i1 = faces[f * 3 + 1], i2 = faces[f * 3 + 2];
    const float* vb = verts + b * V_ * 3;
    float x0 = vb[i0 * 3 + 0], y0 = -vb[i0 * 3 + 1];
    float x1 = vb[i1 * 3 + 0], y1 = -vb[i1 * 3 + 1];
    float x2 = vb[i2 * 3 + 0], y2 = -vb[i2 * 3 + 1];
    float area2 = (x1 - x0) * (y2 - y0) - (y1 - y0) * (x2 - x0);
    float sgn = (area2 > 0.f) ? 1.f : ((area2 < 0.f) ? -1.f : 0.f);
    const float INVS = 1.4426950408889634f / 0.01f;  // log2(e)/SIGMA

    float ax[3] = {x0, x1, x2}, ay[3] = {y0, y1, y2};
    float bx[3] = {x1, x2, x0}, by[3] = {y1, y2, y0};
    float* o = g_coeffs + idx * 12;
#pragma unroll
    for (int e = 0; e < 3; e++) {
        float ex = bx[e] - ax[e];
        float ey = by[e] - ay[e];
        float inv_len = 1.0f / (sqrtf(ex * ex + ey * ey) + 1e-8f);
        float k = sgn * inv_len * INVS;
        o[e * 4 + 0] = -k * ey;
        o[e * 4 + 1] = k * ex;
        o[e * 4 + 2] = k * (ey * ax[e] - ex * ay[e]);
        o[e * 4 + 3] = 0.f;
    }
}

__device__ __forceinline__ float ex2f(float x) {
    float r; asm("ex2.approx.ftz.f32 %0, %1;" : "=f"(r) : "f"(x)); return r;
}
__device__ __forceinline__ float rcpf(float x) {
    float r; asm("rcp.approx.ftz.f32 %0, %1;" : "=f"(r) : "f"(x)); return r;
}

__global__ __launch_bounds__(256) void silhouette_kernel(float* __restrict__ out) {
    __shared__ float4 s_face[CHUNK * 3];   // compacted (e0,e1,e2) per active face
    __shared__ int s_wcnt[8];
    __shared__ int s_wbase[8];
    __shared__ int s_total;
    __shared__ int s_deep;

    const int tid = threadIdx.x;
    const int w = tid >> 5;
    const int lane = tid & 31;
    const int b = blockIdx.z;
    const int x0 = blockIdx.x * TILE;
    const int y0 = blockIdx.y * TILE;

    if (tid == 0) s_deep = 0;

    // thresholds in (dist/sigma)*log2(e) units
    const float DEAD = -15.8696454f;   // -11*log2e : skip err <= 1.7e-5 per face
    const float DEEP = 21.6404256f;    //  15*log2e : Q <= 9.2e-7 -> clipped RMIN
    const float STEP = 2.0f / S_;

    const float cx = (x0 + 8.0f) * STEP - 1.0f;   // tile center
    const float cy = (y0 + 8.0f) * STEP - 1.0f;
    const float hx = 7.5f * STEP + 1e-4f;         // half extent + margin
    const float hy = hx;

    // this thread's pixel
    const int pxi = x0 + (tid & 15);
    const int pyi = y0 + (tid >> 4);
    const float px = (pxi + 0.5f) * STEP - 1.0f;
    const float py = (pyi + 0.5f) * STEP - 1.0f;

    const float RMIN = 1.0f - (1.0f - 1e-6f);   // exact fp32 clip residue
    float W = 1.0f;

    const float* cb = g_coeffs + (size_t)b * F_ * 12;

    for (int base = 0; base < F_; base += CHUNK) {
        // ---- cull: one face per thread ----
        int f = base + tid;
        bool active = false, deep = false;
        float4 e0, e1, e2;
        if (f < F_) {
            const float4* cp = (const float4*)(cb + (size_t)f * 12);
            e0 = __ldg(cp); e1 = __ldg(cp + 1); e2 = __ldg(cp + 2);
            float dc0 = fmaf(e0.x, cx, fmaf(e0.y, cy, e0.z));
            float dc1 = fmaf(e1.x, cx, fmaf(e1.y, cy, e1.z));
            float dc2 = fmaf(e2.x, cx, fmaf(e2.y, cy, e2.z));
            float x0e = fmaf(fabsf(e0.x), hx, fabsf(e0.y) * hy);
            float x1e = fmaf(fabsf(e1.x), hx, fabsf(e1.y) * hy);
            float x2e = fmaf(fabsf(e2.x), hx, fabsf(e2.y) * hy);
            bool dead = (dc0 + x0e < DEAD) || (dc1 + x1e < DEAD) || (dc2 + x2e < DEAD);
            deep = (dc0 - x0e > DEEP) && (dc1 - x1e > DEEP) && (dc2 - x2e > DEEP);
            active = !dead && !deep;
        }
        unsigned balA = __ballot_sync(0xffffffffu, active);
        unsigned balD = __ballot_sync(0xffffffffu, deep);
        if (lane == 0) {
            s_wcnt[w] = __popc(balA);
            if (balD) atomicAdd(&s_deep, __popc(balD));
        }
        __syncthreads();
        if (tid == 0) {   // 8-entry exclusive scan (deterministic compaction order)
            int acc = 0;
#pragma unroll
            for (int i = 0; i < 8; i++) { s_wbase[i] = acc; acc += s_wcnt[i]; }
            s_total = acc;
        }
        __syncthreads();
        if (active) {
            int pos = s_wbase[w] + __popc(balA & ((1u << lane) - 1u));
            s_face[pos * 3 + 0] = e0;
            s_face[pos * 3 + 1] = e1;
            s_face[pos * 3 + 2] = e2;
        }
        __syncthreads();

        // ---- eval: every thread (pixel) over the compacted face list ----
        const int n = s_total;
#pragma unroll 1
        for (int j = 0; j < n; j++) {
            float4 f0 = s_face[j * 3 + 0];
            float4 f1 = s_face[j * 3 + 1];
            float4 f2 = s_face[j * 3 + 2];
            float d0 = fmaf(f0.x, px, fmaf(f0.y, py, f0.z));
            float d1 = fmaf(f1.x, px, fmaf(f1.y, py, f1.z));
            float d2 = fmaf(f2.x, px, fmaf(f2.y, py, f2.z));
            float mn01 = fminf(d0, d1), mx01 = fmaxf(d0, d1);
            float dmin = fminf(mn01, d2);
            float dmid = fmaxf(fminf(mx01, d2), mn01);
            if (dmin > DEAD) {
                float r;
                if (dmid > DEEP) {
                    if (dmin > DEEP) {
                        r = RMIN;                         // fully inside: clipped
                    } else {
                        float t = ex2f(-dmin);            // one relevant edge
                        r = fmaxf(t * rcpf(1.0f + t), RMIN);
                    }
                } else {
                    float t0 = ex2f(-d0);
                    float t1 = ex2f(-d1);
                    float t2 = ex2f(-d2);
                    float sA = t1 + t2;
                    float pA = t1 * t2;
                    float sp = sA + pA;
                    float Q = fmaf(t0, sp, t0 + sp);
                    r = Q * rcpf(1.0f + Q);
                    r = fminf(fmaxf(r, RMIN), 1.0f);
                }
                W *= r;
            }
        }
        __syncthreads();   // protect s_face before next pass overwrites
    }

    // fold in deep (fully-covering) faces: exact clipped constant per face
    int nd = s_deep;
    if (nd >= 8) {
        W = 0.0f;
    } else {
        for (int i = 0; i < nd; i++) W *= RMIN;
    }

    out[((size_t)b * S_ + pyi) * S_ + pxi] = 1.0f - W;
}

extern "C" void kernel_launch(void* const* d_in, const int* in_sizes, int n_in,
                              void* d_out, int out_size) {
    const float* verts = (const float*)d_in[0];
    const int* faces = (const int*)d_in[1];
    float* out = (float*)d_out;

    int total = B_ * F_;
    precompute_kernel<<<(total + 255) / 256, 256>>>(verts, faces);

    dim3 grid(S_ / TILE, S_ / TILE, B_);
    silhouette_kernel<<<grid, 256>>>(out);
}